// round 7
// baseline (speedup 1.0000x reference)
#include <cuda_runtime.h>
#include <cuda_bf16.h>
#include <cstdint>

#define NN 100000
#define NE 1600000
#define HDIM 128

// ---------------- static device scratch ----------------
__device__ float4 g_bufB[(size_t)NN * 32];   // pre-BN linear output (GEMM1 out)
__device__ float4 g_bufC[(size_t)NN * 32];   // layer outputs (GIN block out)

__device__ int g_counts[NN];
__device__ int g_scanTmp[NN];
__device__ int g_partials[128];
__device__ int g_rowptr[NN + 1];
__device__ int g_cursor[NN];
__device__ int g_srcSorted[NE];
__device__ int g_is64;

__device__ float g_Ssum[HDIM];
__device__ float g_Ssq[HDIM];
__device__ float g_scale[HDIM];
__device__ float g_shift[HDIM];

// Pre-split weights, transposed to [n][k] bf16 (hi / lo), 16B-aligned storage.
__device__ uint4 g_WtHi[128 * 128 * 2 / 16];
__device__ uint4 g_WtLo[128 * 128 * 2 / 16];

__device__ __forceinline__ int edge_at(const int* __restrict__ ei, long long pos, int is64) {
    return is64 ? ei[2 * pos] : ei[(size_t)pos];
}

// ---------------- dtype detector ----------------
__global__ void k_detect(const int* __restrict__ ei) {
    __shared__ int nz;
    if (threadIdx.x == 0) nz = 0;
    __syncthreads();
    long long p = (long long)threadIdx.x * (NE / 256);
    if (ei[2 * p + 1] != 0) atomicAdd(&nz, 1);
    __syncthreads();
    if (threadIdx.x == 0) g_is64 = (nz == 0) ? 1 : 0;
}

// ---------------- CSR build ----------------
__global__ void k_zero_counts() {
    int i = blockIdx.x * blockDim.x + threadIdx.x;
    if (i < NN) g_counts[i] = 0;
}

__global__ void k_hist(const int* __restrict__ ei) {
    int e = blockIdx.x * blockDim.x + threadIdx.x;
    if (e < NE) {
        int is64 = g_is64;
        unsigned d = (unsigned)edge_at(ei, (long long)NE + e, is64);
        if (d < NN) atomicAdd(&g_counts[d], 1);
    }
}

__global__ void k_scan1() {
    __shared__ int s[1024];
    int idx = blockIdx.x * 1024 + threadIdx.x;
    int v = (idx < NN) ? g_counts[idx] : 0;
    s[threadIdx.x] = v;
    __syncthreads();
    for (int off = 1; off < 1024; off <<= 1) {
        int t = 0;
        if (threadIdx.x >= off) t = s[threadIdx.x - off];
        __syncthreads();
        s[threadIdx.x] += t;
        __syncthreads();
    }
    if (idx < NN) g_scanTmp[idx] = s[threadIdx.x];
    if (threadIdx.x == 1023) g_partials[blockIdx.x] = s[1023];
}

__global__ void k_scan2(int nblocks) {
    __shared__ int s[128];
    int t = threadIdx.x;
    int v = (t < nblocks) ? g_partials[t] : 0;
    s[t] = v;
    __syncthreads();
    for (int off = 1; off < 128; off <<= 1) {
        int tv = 0;
        if (t >= off) tv = s[t - off];
        __syncthreads();
        s[t] += tv;
        __syncthreads();
    }
    g_partials[t] = s[t];
    if (t == 0) g_rowptr[0] = 0;
}

__global__ void k_scan3() {
    int idx = blockIdx.x * 1024 + threadIdx.x;
    if (idx < NN) {
        int off = (blockIdx.x > 0) ? g_partials[blockIdx.x - 1] : 0;
        int incl = g_scanTmp[idx] + off;
        int excl = incl - g_counts[idx];
        g_rowptr[idx] = excl;
        g_cursor[idx] = excl;
        if (idx == NN - 1) g_rowptr[NN] = incl;
    }
}

__global__ void k_scatter(const int* __restrict__ ei) {
    int e = blockIdx.x * blockDim.x + threadIdx.x;
    if (e < NE) {
        int is64 = g_is64;
        int s = edge_at(ei, e, is64);
        unsigned d = (unsigned)edge_at(ei, (long long)NE + e, is64);
        if (d < NN) {
            int pos = atomicAdd(&g_cursor[d], 1);
            g_srcSorted[pos] = s;
        }
    }
}

// ---------------- BN helpers ----------------
__global__ void k_zero_stats() {
    int j = threadIdx.x;
    if (j < HDIM) { g_Ssum[j] = 0.f; g_Ssq[j] = 0.f; }
}

// finalize + re-zero stats for the next layer
__global__ void k_bn_finalize(const float* __restrict__ gamma, const float* __restrict__ beta) {
    int j = threadIdx.x;
    if (j < HDIM) {
        float mu = g_Ssum[j] / (float)NN;
        float var = g_Ssq[j] / (float)NN - mu * mu;
        var = fmaxf(var, 0.f);
        float sc = gamma[j] * rsqrtf(var + 1e-5f);
        g_scale[j] = sc;
        g_shift[j] = beta[j] - mu * sc;
        g_Ssum[j] = 0.f;
        g_Ssq[j] = 0.f;
    }
}

// ---------------- weight pre-split: W[K][128] fp32 -> Wt hi/lo [128][K] bf16 ----------------
__global__ void k_prepW(const float* __restrict__ W, int K) {
    int idx = blockIdx.x * 256 + threadIdx.x;
    if (idx < K * 128) {
        int k = idx >> 7, n = idx & 127;
        float v = W[idx];
        __nv_bfloat16 hi = __float2bfloat16(v);
        __nv_bfloat16 lo = __float2bfloat16(v - __bfloat162float(hi));
        ((__nv_bfloat16*)g_WtHi)[n * K + k] = hi;
        ((__nv_bfloat16*)g_WtLo)[n * K + k] = lo;
    }
}

// ---------------- MMA primitive ----------------
__device__ __forceinline__ void mma_bf16(float* d, const uint32_t* a, const uint32_t* b) {
    asm volatile(
        "mma.sync.aligned.m16n8k16.row.col.f32.bf16.bf16.f32 "
        "{%0,%1,%2,%3}, {%4,%5,%6,%7}, {%8,%9}, {%0,%1,%2,%3};\n"
        : "+f"(d[0]), "+f"(d[1]), "+f"(d[2]), "+f"(d[3])
        : "r"(a[0]), "r"(a[1]), "r"(a[2]), "r"(a[3]), "r"(b[0]), "r"(b[1]));
}

// =====================================================================
// Fused GIN stage 1: aggregation + GEMM(wa) + bias + column stats.
//   K=64 : reads external x ;  K=128 : reads g_bufC.   Output: g_bufB.
// Dynamic smem: sAhi/sAlo full-K (pitch K+2), sBhi/sBlo per-chunk, sums.
// =====================================================================
template<int K>
__global__ void __launch_bounds__(256)
k_gin1(const float* __restrict__ xext, const float* __restrict__ epsp,
       const float* __restrict__ bias) {
    constexpr int AP = K + 2;          // bf16 pitch (padded: kills 8-way LDS conflicts)
    constexpr int APW = AP / 2;        // uint32 pitch
    extern __shared__ char smem[];
    __nv_bfloat16* sAhi = (__nv_bfloat16*)smem;
    __nv_bfloat16* sAlo = sAhi + 128 * AP;
    __nv_bfloat16* sBhi = sAlo + 128 * AP;
    __nv_bfloat16* sBlo = sBhi + 128 * 16;
    float* sSum = (float*)(sBlo + 128 * 16);
    float* sSq = sSum + 128;

    const int tid = threadIdx.x;
    const int lane = tid & 31;
    const int warp = tid >> 5;
    const int rowBase = blockIdx.x * 128;
    if (tid < 128) { sSum[tid] = 0.f; sSq[tid] = 0.f; }

    const float eps1 = 1.0f + *epsp;

    // ---- phase 1: gather + (1+eps)*self, convert to hi/lo bf16 in smem ----
    for (int t = 0; t < 16; t++) {
        int i = warp * 16 + t;
        int node = rowBase + i;
        if (K == 64) {
            float2 acc = make_float2(0.f, 0.f);
            if (node < NN) {
                const float2* xb = (const float2*)xext;
                float2 self = xb[(size_t)node * 32 + lane];
                acc.x = self.x * eps1; acc.y = self.y * eps1;
                int lo = g_rowptr[node], hi = g_rowptr[node + 1];
                for (int e = lo; e < hi; ++e) {
                    int s = g_srcSorted[e];
                    if ((unsigned)s < NN) {
                        float2 v = xb[(size_t)s * 32 + lane];
                        acc.x += v.x; acc.y += v.y;
                    }
                }
            }
            int c0 = lane * 2;
            float vals[2] = {acc.x, acc.y};
#pragma unroll
            for (int j = 0; j < 2; j++) {
                __nv_bfloat16 h = __float2bfloat16(vals[j]);
                sAhi[i * AP + c0 + j] = h;
                sAlo[i * AP + c0 + j] = __float2bfloat16(vals[j] - __bfloat162float(h));
            }
        } else {
            float4 acc = make_float4(0.f, 0.f, 0.f, 0.f);
            if (node < NN) {
                const float4* xb = g_bufC;
                float4 self = xb[(size_t)node * 32 + lane];
                acc.x = self.x * eps1; acc.y = self.y * eps1;
                acc.z = self.z * eps1; acc.w = self.w * eps1;
                int lo = g_rowptr[node], hi = g_rowptr[node + 1];
                for (int e = lo; e < hi; ++e) {
                    int s = g_srcSorted[e];
                    if ((unsigned)s < NN) {
                        float4 v = xb[(size_t)s * 32 + lane];
                        acc.x += v.x; acc.y += v.y; acc.z += v.z; acc.w += v.w;
                    }
                }
            }
            int c0 = lane * 4;
            float vals[4] = {acc.x, acc.y, acc.z, acc.w};
#pragma unroll
            for (int j = 0; j < 4; j++) {
                __nv_bfloat16 h = __float2bfloat16(vals[j]);
                sAhi[i * AP + c0 + j] = h;
                sAlo[i * AP + c0 + j] = __float2bfloat16(vals[j] - __bfloat162float(h));
            }
        }
    }
    __syncthreads();

    // ---- phase 2: split-bf16 MMA ----
    const __nv_bfloat16* pWhi = (const __nv_bfloat16*)g_WtHi;
    const __nv_bfloat16* pWlo = (const __nv_bfloat16*)g_WtLo;
    const int wm = warp & 3;
    const int wn = warp >> 2;
    const int qr = lane >> 2;
    const int qc = lane & 3;

    float acc[2][8][4];
#pragma unroll
    for (int m = 0; m < 2; m++)
#pragma unroll
        for (int n = 0; n < 8; n++)
#pragma unroll
            for (int j = 0; j < 4; j++) acc[m][n][j] = 0.f;

    const uint32_t* a32h = (const uint32_t*)sAhi;
    const uint32_t* a32l = (const uint32_t*)sAlo;

    for (int kk = 0; kk < K; kk += 16) {
        {
            int n = tid >> 1, half = tid & 1;
            *(uint4*)(sBhi + n * 16 + half * 8) =
                *(const uint4*)(pWhi + (size_t)n * K + kk + half * 8);
            *(uint4*)(sBlo + n * 16 + half * 8) =
                *(const uint4*)(pWlo + (size_t)n * K + kk + half * 8);
        }
        __syncthreads();
        const uint32_t* b32h = (const uint32_t*)sBhi;
        const uint32_t* b32l = (const uint32_t*)sBlo;

        uint32_t bh[8][2], bl[8][2];
#pragma unroll
        for (int n = 0; n < 8; n++) {
            int nrow = wn * 64 + n * 8 + qr;
            bh[n][0] = b32h[nrow * 8 + qc];
            bh[n][1] = b32h[nrow * 8 + 4 + qc];
            bl[n][0] = b32l[nrow * 8 + qc];
            bl[n][1] = b32l[nrow * 8 + 4 + qc];
        }
#pragma unroll
        for (int m = 0; m < 2; m++) {
            int r = wm * 32 + m * 16 + qr;
            uint32_t ah[4], al[4];
            ah[0] = a32h[r * APW + kk / 2 + qc];
            ah[1] = a32h[(r + 8) * APW + kk / 2 + qc];
            ah[2] = a32h[r * APW + kk / 2 + 4 + qc];
            ah[3] = a32h[(r + 8) * APW + kk / 2 + 4 + qc];
            al[0] = a32l[r * APW + kk / 2 + qc];
            al[1] = a32l[(r + 8) * APW + kk / 2 + qc];
            al[2] = a32l[r * APW + kk / 2 + 4 + qc];
            al[3] = a32l[(r + 8) * APW + kk / 2 + 4 + qc];
#pragma unroll
            for (int n = 0; n < 8; n++) {
                mma_bf16(acc[m][n], ah, bh[n]);
                mma_bf16(acc[m][n], ah, bl[n]);
                mma_bf16(acc[m][n], al, bh[n]);
            }
        }
        __syncthreads();
    }

    // ---- epilogue: bias, store to g_bufB, column stats ----
    float* out = (float*)g_bufB;
    float cS[16], cQ[16];
#pragma unroll
    for (int j = 0; j < 16; j++) { cS[j] = 0.f; cQ[j] = 0.f; }

#pragma unroll
    for (int m = 0; m < 2; m++) {
        int r = rowBase + wm * 32 + m * 16 + qr;
#pragma unroll
        for (int n = 0; n < 8; n++) {
            int c = wn * 64 + n * 8 + qc * 2;
            float b0 = bias[c], b1 = bias[c + 1];
            float v0 = acc[m][n][0] + b0, v1 = acc[m][n][1] + b1;
            float v2 = acc[m][n][2] + b0, v3 = acc[m][n][3] + b1;
            if (r < NN) {
                *(float2*)(out + (size_t)r * 128 + c) = make_float2(v0, v1);
                cS[n * 2] += v0; cS[n * 2 + 1] += v1;
                cQ[n * 2] += v0 * v0; cQ[n * 2 + 1] += v1 * v1;
            }
            if (r + 8 < NN) {
                *(float2*)(out + (size_t)(r + 8) * 128 + c) = make_float2(v2, v3);
                cS[n * 2] += v2; cS[n * 2 + 1] += v3;
                cQ[n * 2] += v2 * v2; cQ[n * 2 + 1] += v3 * v3;
            }
        }
    }
#pragma unroll
    for (int n = 0; n < 8; n++) {
        int c = wn * 64 + n * 8 + qc * 2;
        atomicAdd(&sSum[c], cS[n * 2]);
        atomicAdd(&sSum[c + 1], cS[n * 2 + 1]);
        atomicAdd(&sSq[c], cQ[n * 2]);
        atomicAdd(&sSq[c + 1], cQ[n * 2 + 1]);
    }
    __syncthreads();
    if (tid < 128) {
        atomicAdd(&g_Ssum[tid], sSum[tid]);
        atomicAdd(&g_Ssq[tid], sSq[tid]);
    }
}

// =====================================================================
// GIN stage 2: BN+relu on input, GEMM(wb) + bias, relu out. bufB -> bufC
// =====================================================================
__global__ void __launch_bounds__(256)
k_gemm2(const float* __restrict__ bias) {
    const float* A = (const float*)g_bufB;
    float* out = (float*)g_bufC;
    const __nv_bfloat16* pWhi = (const __nv_bfloat16*)g_WtHi;
    const __nv_bfloat16* pWlo = (const __nv_bfloat16*)g_WtLo;
    constexpr int K = 128;

    __shared__ __align__(16) __nv_bfloat16 sAhi[128 * 16];
    __shared__ __align__(16) __nv_bfloat16 sAlo[128 * 16];
    __shared__ __align__(16) __nv_bfloat16 sBhi[128 * 16];
    __shared__ __align__(16) __nv_bfloat16 sBlo[128 * 16];

    const int tid = threadIdx.x;
    const int lane = tid & 31;
    const int warp = tid >> 5;
    const int wm = warp & 3;
    const int wn = warp >> 2;
    const int qr = lane >> 2;
    const int qc = lane & 3;
    const int rowBase = blockIdx.x * 128;

    float acc[2][8][4];
#pragma unroll
    for (int m = 0; m < 2; m++)
#pragma unroll
        for (int n = 0; n < 8; n++)
#pragma unroll
            for (int j = 0; j < 4; j++) acc[m][n][j] = 0.f;

    for (int kk = 0; kk < K; kk += 16) {
#pragma unroll
        for (int it = 0; it < 2; it++) {
            int f = it * 256 + tid;
            int row = f >> 2;
            int c4 = (f & 3) << 2;
            int gr = rowBase + row;
            float4 v = make_float4(0.f, 0.f, 0.f, 0.f);
            if (gr < NN) v = *(const float4*)(A + (size_t)gr * K + kk + c4);
            float vals[4] = {v.x, v.y, v.z, v.w};
#pragma unroll
            for (int j = 0; j < 4; j++) {
                int kb = kk + c4 + j;
                float val = fmaxf(vals[j] * g_scale[kb] + g_shift[kb], 0.f);
                __nv_bfloat16 h = __float2bfloat16(val);
                sAhi[row * 16 + c4 + j] = h;
                sAlo[row * 16 + c4 + j] = __float2bfloat16(val - __bfloat162float(h));
            }
        }
        {
            int n = tid >> 1, half = tid & 1;
            *(uint4*)(sBhi + n * 16 + half * 8) =
                *(const uint4*)(pWhi + (size_t)n * K + kk + half * 8);
            *(uint4*)(sBlo + n * 16 + half * 8) =
                *(const uint4*)(pWlo + (size_t)n * K + kk + half * 8);
        }
        __syncthreads();

        const uint32_t* a32h = (const uint32_t*)sAhi;
        const uint32_t* a32l = (const uint32_t*)sAlo;
        const uint32_t* b32h = (const uint32_t*)sBhi;
        const uint32_t* b32l = (const uint32_t*)sBlo;

        uint32_t bh[8][2], bl[8][2];
#pragma unroll
        for (int n = 0; n < 8; n++) {
            int nrow = wn * 64 + n * 8 + qr;
            bh[n][0] = b32h[nrow * 8 + qc];
            bh[n][1] = b32h[nrow * 8 + 4 + qc];
            bl[n][0] = b32l[nrow * 8 + qc];
            bl[n][1] = b32l[nrow * 8 + 4 + qc];
        }
#pragma unroll
        for (int m = 0; m < 2; m++) {
            int r = wm * 32 + m * 16 + qr;
            uint32_t ah[4], al[4];
            ah[0] = a32h[r * 8 + qc];
            ah[1] = a32h[(r + 8) * 8 + qc];
            ah[2] = a32h[r * 8 + 4 + qc];
            ah[3] = a32h[(r + 8) * 8 + 4 + qc];
            al[0] = a32l[r * 8 + qc];
            al[1] = a32l[(r + 8) * 8 + qc];
            al[2] = a32l[r * 8 + 4 + qc];
            al[3] = a32l[(r + 8) * 8 + 4 + qc];
#pragma unroll
            for (int n = 0; n < 8; n++) {
                mma_bf16(acc[m][n], ah, bh[n]);
                mma_bf16(acc[m][n], ah, bl[n]);
                mma_bf16(acc[m][n], al, bh[n]);
            }
        }
        __syncthreads();
    }

#pragma unroll
    for (int m = 0; m < 2; m++) {
        int r = rowBase + wm * 32 + m * 16 + qr;
#pragma unroll
        for (int n = 0; n < 8; n++) {
            int c = wn * 64 + n * 8 + qc * 2;
            float b0 = bias[c], b1 = bias[c + 1];
            float v0 = fmaxf(acc[m][n][0] + b0, 0.f), v1 = fmaxf(acc[m][n][1] + b1, 0.f);
            float v2 = fmaxf(acc[m][n][2] + b0, 0.f), v3 = fmaxf(acc[m][n][3] + b1, 0.f);
            if (r < NN)
                *(float2*)(out + (size_t)r * 128 + c) = make_float2(v0, v1);
            if (r + 8 < NN)
                *(float2*)(out + (size_t)(r + 8) * 128 + c) = make_float2(v2, v3);
        }
    }
}

// =====================================================================
// Fused head: relu(bufC @ hwa + hba) @ hwb + hbb -> out  (no 51MB temp)
// =====================================================================
__global__ void __launch_bounds__(256)
k_headgemm(const float* __restrict__ hba, const float* __restrict__ hwb,
           const float* __restrict__ hbb, float* __restrict__ out) {
    const float* A = (const float*)g_bufC;
    const __nv_bfloat16* pWhi = (const __nv_bfloat16*)g_WtHi;
    const __nv_bfloat16* pWlo = (const __nv_bfloat16*)g_WtLo;
    constexpr int K = 128;

    __shared__ __align__(16) __nv_bfloat16 sAhi[128 * 16];
    __shared__ __align__(16) __nv_bfloat16 sAlo[128 * 16];
    __shared__ __align__(16) __nv_bfloat16 sBhi[128 * 16];
    __shared__ __align__(16) __nv_bfloat16 sBlo[128 * 16];
    __shared__ float sW2[256];
    __shared__ float sOut[256];

    const int tid = threadIdx.x;
    const int lane = tid & 31;
    const int warp = tid >> 5;
    const int wm = warp & 3;
    const int wn = warp >> 2;
    const int qr = lane >> 2;
    const int qc = lane & 3;
    const int rowBase = blockIdx.x * 128;

    sW2[tid] = hwb[tid];    // 128x2 row-major (k-major)
    sOut[tid] = 0.f;

    float acc[2][8][4];
#pragma unroll
    for (int m = 0; m < 2; m++)
#pragma unroll
        for (int n = 0; n < 8; n++)
#pragma unroll
            for (int j = 0; j < 4; j++) acc[m][n][j] = 0.f;

    for (int kk = 0; kk < K; kk += 16) {
#pragma unroll
        for (int it = 0; it < 2; it++) {
            int f = it * 256 + tid;
            int row = f >> 2;
            int c4 = (f & 3) << 2;
            int gr = rowBase + row;
            float4 v = make_float4(0.f, 0.f, 0.f, 0.f);
            if (gr < NN) v = *(const float4*)(A + (size_t)gr * K + kk + c4);
            float vals[4] = {v.x, v.y, v.z, v.w};
#pragma unroll
            for (int j = 0; j < 4; j++) {
                __nv_bfloat16 h = __float2bfloat16(vals[j]);
                sAhi[row * 16 + c4 + j] = h;
                sAlo[row * 16 + c4 + j] = __float2bfloat16(vals[j] - __bfloat162float(h));
            }
        }
        {
            int n = tid >> 1, half = tid & 1;
            *(uint4*)(sBhi + n * 16 + half * 8) =
                *(const uint4*)(pWhi + (size_t)n * K + kk + half * 8);
            *(uint4*)(sBlo + n * 16 + half * 8) =
                *(const uint4*)(pWlo + (size_t)n * K + kk + half * 8);
        }
        __syncthreads();

        const uint32_t* a32h = (const uint32_t*)sAhi;
        const uint32_t* a32l = (const uint32_t*)sAlo;
        const uint32_t* b32h = (const uint32_t*)sBhi;
        const uint32_t* b32l = (const uint32_t*)sBlo;

        uint32_t bh[8][2], bl[8][2];
#pragma unroll
        for (int n = 0; n < 8; n++) {
            int nrow = wn * 64 + n * 8 + qr;
            bh[n][0] = b32h[nrow * 8 + qc];
            bh[n][1] = b32h[nrow * 8 + 4 + qc];
            bl[n][0] = b32l[nrow * 8 + qc];
            bl[n][1] = b32l[nrow * 8 + 4 + qc];
        }
#pragma unroll
        for (int m = 0; m < 2; m++) {
            int r = wm * 32 + m * 16 + qr;
            uint32_t ah[4], al[4];
            ah[0] = a32h[r * 8 + qc];
            ah[1] = a32h[(r + 8) * 8 + qc];
            ah[2] = a32h[r * 8 + 4 + qc];
            ah[3] = a32h[(r + 8) * 8 + 4 + qc];
            al[0] = a32l[r * 8 + qc];
            al[1] = a32l[(r + 8) * 8 + qc];
            al[2] = a32l[r * 8 + 4 + qc];
            al[3] = a32l[(r + 8) * 8 + 4 + qc];
#pragma unroll
            for (int n = 0; n < 8; n++) {
                mma_bf16(acc[m][n], ah, bh[n]);
                mma_bf16(acc[m][n], ah, bl[n]);
                mma_bf16(acc[m][n], al, bh[n]);
            }
        }
        __syncthreads();
    }

    // epilogue: bias + relu, then project 128 -> 2 via smem accumulation
#pragma unroll
    for (int m = 0; m < 2; m++) {
        int rl = wm * 32 + m * 16 + qr;
#pragma unroll
        for (int n = 0; n < 8; n++) {
            int c = wn * 64 + n * 8 + qc * 2;
            float b0 = hba[c], b1 = hba[c + 1];
            float v0 = fmaxf(acc[m][n][0] + b0, 0.f), v1 = fmaxf(acc[m][n][1] + b1, 0.f);
            float v2 = fmaxf(acc[m][n][2] + b0, 0.f), v3 = fmaxf(acc[m][n][3] + b1, 0.f);
            float w00 = sW2[c * 2 + 0], w01 = sW2[c * 2 + 1];
            float w10 = sW2[(c + 1) * 2 + 0], w11 = sW2[(c + 1) * 2 + 1];
            if (rowBase + rl < NN) {
                atomicAdd(&sOut[rl * 2 + 0], v0 * w00 + v1 * w10);
                atomicAdd(&sOut[rl * 2 + 1], v0 * w01 + v1 * w11);
            }
            if (rowBase + rl + 8 < NN) {
                atomicAdd(&sOut[(rl + 8) * 2 + 0], v2 * w00 + v3 * w10);
                atomicAdd(&sOut[(rl + 8) * 2 + 1], v2 * w01 + v3 * w11);
            }
        }
    }
    __syncthreads();
    if (tid < 128) {
        int r = rowBase + tid;
        if (r < NN) {
            out[(size_t)r * 2 + 0] = sOut[tid * 2 + 0] + hbb[0];
            out[(size_t)r * 2 + 1] = sOut[tid * 2 + 1] + hbb[1];
        }
    }
}

// ---------------- launch ----------------
extern "C" void kernel_launch(void* const* d_in, const int* in_sizes, int n_in,
                              void* d_out, int out_size) {
    const float* x = (const float*)d_in[0];
    const int* ei = (const int*)d_in[1];

    const float* wa[3]; const float* ba[3]; const float* gm[3]; const float* be[3];
    const float* wb[3]; const float* bb[3]; const float* ep[3];
    for (int l = 0; l < 3; l++) {
        int b = 2 + 7 * l;
        wa[l] = (const float*)d_in[b + 0];
        ba[l] = (const float*)d_in[b + 1];
        gm[l] = (const float*)d_in[b + 2];
        be[l] = (const float*)d_in[b + 3];
        wb[l] = (const float*)d_in[b + 4];
        bb[l] = (const float*)d_in[b + 5];
        ep[l] = (const float*)d_in[b + 6];
    }
    const float* hwa = (const float*)d_in[23];
    const float* hba = (const float*)d_in[24];
    const float* hwb = (const float*)d_in[25];
    const float* hbb = (const float*)d_in[26];
    float* out = (float*)d_out;

    const int NB1 = (NN + 1023) / 1024;       // 98
    const int GB = (NN + 127) / 128;           // 782
    const int PW64 = (64 * 128 + 255) / 256;   // 32
    const int PW128 = (128 * 128 + 255) / 256; // 64

    // dynamic smem sizes for k_gin1 (A hi/lo full-K padded + B chunk + stats)
    const int SMEM64 = 128 * (64 + 2) * 2 * 2 + 128 * 16 * 2 * 2 + 256 * 4;   // 43 KB
    const int SMEM128 = 128 * (128 + 2) * 2 * 2 + 128 * 16 * 2 * 2 + 256 * 4; // 76 KB
    cudaFuncSetAttribute(k_gin1<64>, cudaFuncAttributeMaxDynamicSharedMemorySize, SMEM64);
    cudaFuncSetAttribute(k_gin1<128>, cudaFuncAttributeMaxDynamicSharedMemorySize, SMEM128);

    // edge dtype detection + CSR build (reused by all 3 layers)
    k_detect<<<1, 256>>>(ei);
    k_zero_counts<<<(NN + 255) / 256, 256>>>();
    k_hist<<<(NE + 255) / 256, 256>>>(ei);
    k_scan1<<<NB1, 1024>>>();
    k_scan2<<<1, 128>>>(NB1);
    k_scan3<<<NB1, 1024>>>();
    k_scatter<<<(NE + 255) / 256, 256>>>(ei);
    k_zero_stats<<<1, 128>>>();

    // ---- layer 0 (din = 64): x --(agg+gemm1)--> bufB --(bn+gemm2)--> bufC ----
    k_prepW<<<PW64, 256>>>(wa[0], 64);
    k_gin1<64><<<GB, 256, SMEM64>>>(x, ep[0], ba[0]);
    k_bn_finalize<<<1, 128>>>(gm[0], be[0]);
    k_prepW<<<PW128, 256>>>(wb[0], 128);
    k_gemm2<<<GB, 256>>>(bb[0]);

    // ---- layers 1,2 (din = 128): bufC --(agg+gemm1)--> bufB --> bufC ----
    for (int l = 1; l < 3; l++) {
        k_prepW<<<PW128, 256>>>(wa[l], 128);
        k_gin1<128><<<GB, 256, SMEM128>>>(nullptr, ep[l], ba[l]);
        k_bn_finalize<<<1, 128>>>(gm[l], be[l]);
        k_prepW<<<PW128, 256>>>(wb[l], 128);
        k_gemm2<<<GB, 256>>>(bb[l]);
    }

    // ---- fused head: bufC -> out ----
    k_prepW<<<PW128, 256>>>(hwa, 128);
    k_headgemm<<<GB, 256>>>(hba, hwb, hbb, out);
}

// round 8
// speedup vs baseline: 1.2238x; 1.2238x over previous
#include <cuda_runtime.h>
#include <cuda_bf16.h>
#include <cstdint>

#define NN 100000
#define NE 1600000
#define HDIM 128

// ---------------- static device scratch ----------------
__device__ float4 g_bufA[(size_t)NN * 32];   // agg output (N x K)
__device__ float4 g_bufB[(size_t)NN * 32];   // pre-BN linear output
__device__ float4 g_bufC[(size_t)NN * 32];   // layer outputs

__device__ int g_counts[NN];
__device__ int g_scanTmp[NN];
__device__ int g_partials[128];
__device__ int g_rowptr[NN + 1];
__device__ int g_cursor[NN];
__device__ int g_srcSorted[NE];
__device__ int g_is64;

__device__ float g_Ssum[HDIM];
__device__ float g_Ssq[HDIM];
__device__ float g_scale[HDIM];
__device__ float g_shift[HDIM];

// Pre-split weights: 7 slots, each [128][K] bf16 hi/lo (transposed to n-major).
// Slot s at offset s*16384 elements.
__device__ uint4 g_WtHi[7 * 128 * 128 * 2 / 16];
__device__ uint4 g_WtLo[7 * 128 * 128 * 2 / 16];

template<int B> __device__ __forceinline__ float* bufsel();
template<> __device__ __forceinline__ float* bufsel<0>() { return (float*)g_bufA; }
template<> __device__ __forceinline__ float* bufsel<1>() { return (float*)g_bufB; }
template<> __device__ __forceinline__ float* bufsel<2>() { return (float*)g_bufC; }

__device__ __forceinline__ int edge_at(const int* __restrict__ ei, long long pos, int is64) {
    return is64 ? ei[2 * pos] : ei[(size_t)pos];
}

// ---------------- dtype detector ----------------
__global__ void k_detect(const int* __restrict__ ei) {
    __shared__ int nz;
    if (threadIdx.x == 0) nz = 0;
    __syncthreads();
    long long p = (long long)threadIdx.x * (NE / 256);
    if (ei[2 * p + 1] != 0) atomicAdd(&nz, 1);
    __syncthreads();
    if (threadIdx.x == 0) g_is64 = (nz == 0) ? 1 : 0;
}

// ---------------- CSR build ----------------
__global__ void k_zero_counts() {
    int i = blockIdx.x * blockDim.x + threadIdx.x;
    if (i < NN) g_counts[i] = 0;
}

__global__ void k_hist(const int* __restrict__ ei) {
    int e = blockIdx.x * blockDim.x + threadIdx.x;
    if (e < NE) {
        int is64 = g_is64;
        unsigned d = (unsigned)edge_at(ei, (long long)NE + e, is64);
        if (d < NN) atomicAdd(&g_counts[d], 1);
    }
}

__global__ void k_scan1() {
    __shared__ int s[1024];
    int idx = blockIdx.x * 1024 + threadIdx.x;
    int v = (idx < NN) ? g_counts[idx] : 0;
    s[threadIdx.x] = v;
    __syncthreads();
    for (int off = 1; off < 1024; off <<= 1) {
        int t = 0;
        if (threadIdx.x >= off) t = s[threadIdx.x - off];
        __syncthreads();
        s[threadIdx.x] += t;
        __syncthreads();
    }
    if (idx < NN) g_scanTmp[idx] = s[threadIdx.x];
    if (threadIdx.x == 1023) g_partials[blockIdx.x] = s[1023];
}

__global__ void k_scan2(int nblocks) {
    __shared__ int s[128];
    int t = threadIdx.x;
    int v = (t < nblocks) ? g_partials[t] : 0;
    s[t] = v;
    __syncthreads();
    for (int off = 1; off < 128; off <<= 1) {
        int tv = 0;
        if (t >= off) tv = s[t - off];
        __syncthreads();
        s[t] += tv;
        __syncthreads();
    }
    g_partials[t] = s[t];
    if (t == 0) g_rowptr[0] = 0;
}

__global__ void k_scan3() {
    int idx = blockIdx.x * 1024 + threadIdx.x;
    if (idx < NN) {
        int off = (blockIdx.x > 0) ? g_partials[blockIdx.x - 1] : 0;
        int incl = g_scanTmp[idx] + off;
        int excl = incl - g_counts[idx];
        g_rowptr[idx] = excl;
        g_cursor[idx] = excl;
        if (idx == NN - 1) g_rowptr[NN] = incl;
    }
}

__global__ void k_scatter(const int* __restrict__ ei) {
    int e = blockIdx.x * blockDim.x + threadIdx.x;
    if (e < NE) {
        int is64 = g_is64;
        int s = edge_at(ei, e, is64);
        unsigned d = (unsigned)edge_at(ei, (long long)NE + e, is64);
        if (d < NN) {
            int pos = atomicAdd(&g_cursor[d], 1);
            g_srcSorted[pos] = s;
        }
    }
}

// ---------------- aggregation: warp per node, gather ----------------
__global__ void k_agg64(const float* __restrict__ x, const float* __restrict__ epsp) {
    int warp = (blockIdx.x * blockDim.x + threadIdx.x) >> 5;
    int lane = threadIdx.x & 31;
    if (warp >= NN) return;
    int lo = g_rowptr[warp], hi = g_rowptr[warp + 1];
    float eps1 = 1.0f + *epsp;
    const float2* xb = (const float2*)x;
    float2 self = xb[(size_t)warp * 32 + lane];
    float2 acc;
    acc.x = self.x * eps1; acc.y = self.y * eps1;
    for (int e = lo; e < hi; ++e) {
        int s = g_srcSorted[e];
        if ((unsigned)s < NN) {
            float2 v = xb[(size_t)s * 32 + lane];
            acc.x += v.x; acc.y += v.y;
        }
    }
    ((float2*)g_bufA)[(size_t)warp * 32 + lane] = acc;
}

__global__ void k_agg128(const float* __restrict__ epsp) {
    int warp = (blockIdx.x * blockDim.x + threadIdx.x) >> 5;
    int lane = threadIdx.x & 31;
    if (warp >= NN) return;
    int lo = g_rowptr[warp], hi = g_rowptr[warp + 1];
    float eps1 = 1.0f + *epsp;
    const float4* xb = g_bufC;
    float4 self = xb[(size_t)warp * 32 + lane];
    float4 acc;
    acc.x = self.x * eps1; acc.y = self.y * eps1;
    acc.z = self.z * eps1; acc.w = self.w * eps1;
    for (int e = lo; e < hi; ++e) {
        int s = g_srcSorted[e];
        if ((unsigned)s < NN) {
            float4 v = xb[(size_t)s * 32 + lane];
            acc.x += v.x; acc.y += v.y; acc.z += v.z; acc.w += v.w;
        }
    }
    g_bufA[(size_t)warp * 32 + lane] = acc;
}

// ---------------- BN helpers ----------------
__global__ void k_zero_stats() {
    int j = threadIdx.x;
    if (j < HDIM) { g_Ssum[j] = 0.f; g_Ssq[j] = 0.f; }
}

// finalize + re-zero stats for the next layer
__global__ void k_bn_finalize(const float* __restrict__ gamma, const float* __restrict__ beta) {
    int j = threadIdx.x;
    if (j < HDIM) {
        float mu = g_Ssum[j] / (float)NN;
        float var = g_Ssq[j] / (float)NN - mu * mu;
        var = fmaxf(var, 0.f);
        float sc = gamma[j] * rsqrtf(var + 1e-5f);
        g_scale[j] = sc;
        g_shift[j] = beta[j] - mu * sc;
        g_Ssum[j] = 0.f;
        g_Ssq[j] = 0.f;
    }
}

// ---------------- one-shot weight pre-split for all 7 matrices ----------------
// grid = (64, 7); slot y, K per slot passed in constant array via params.
__global__ void k_prepAll(const float* __restrict__ w0, const float* __restrict__ w1,
                          const float* __restrict__ w2, const float* __restrict__ w3,
                          const float* __restrict__ w4, const float* __restrict__ w5,
                          const float* __restrict__ w6) {
    int slot = blockIdx.y;
    const float* W;
    int K;
    switch (slot) {
        case 0: W = w0; K = 64; break;
        case 1: W = w1; K = 128; break;
        case 2: W = w2; K = 128; break;
        case 3: W = w3; K = 128; break;
        case 4: W = w4; K = 128; break;
        case 5: W = w5; K = 128; break;
        default: W = w6; K = 128; break;
    }
    int idx = blockIdx.x * 256 + threadIdx.x;
    if (idx < K * 128) {
        int k = idx >> 7, n = idx & 127;
        float v = W[idx];
        __nv_bfloat16 hi = __float2bfloat16(v);
        __nv_bfloat16 lo = __float2bfloat16(v - __bfloat162float(hi));
        size_t off = (size_t)slot * 16384 + (size_t)n * K + k;
        ((__nv_bfloat16*)g_WtHi)[off] = hi;
        ((__nv_bfloat16*)g_WtLo)[off] = lo;
    }
}

// ---------------- MMA primitive ----------------
__device__ __forceinline__ void mma_bf16(float* d, const uint32_t* a, const uint32_t* b) {
    asm volatile(
        "mma.sync.aligned.m16n8k16.row.col.f32.bf16.bf16.f32 "
        "{%0,%1,%2,%3}, {%4,%5,%6,%7}, {%8,%9}, {%0,%1,%2,%3};\n"
        : "+f"(d[0]), "+f"(d[1]), "+f"(d[2]), "+f"(d[3])
        : "r"(a[0]), "r"(a[1]), "r"(a[2]), "r"(a[3]), "r"(b[0]), "r"(b[1]));
}

// ---------------- split-bf16 tensor-core GEMM ----------------
// C[NN x 128] = A[NN x K] @ Wslot[K x 128] (+bias, BN-in / relu-out / stats opts)
template<int K, int SRC, int DST, int SLOT, bool IN_BN, bool OUT_RELU, bool STATS>
__global__ void __launch_bounds__(256)
k_gemm_mma(const float* __restrict__ bias) {
    const float* A = bufsel<SRC>();
    float* out = bufsel<DST>();
    const __nv_bfloat16* pWhi = (const __nv_bfloat16*)g_WtHi + (size_t)SLOT * 16384;
    const __nv_bfloat16* pWlo = (const __nv_bfloat16*)g_WtLo + (size_t)SLOT * 16384;

    __shared__ __align__(16) __nv_bfloat16 sAhi[128 * 16];
    __shared__ __align__(16) __nv_bfloat16 sAlo[128 * 16];
    __shared__ __align__(16) __nv_bfloat16 sBhi[128 * 16];
    __shared__ __align__(16) __nv_bfloat16 sBlo[128 * 16];
    __shared__ float sSum[128], sSq[128];

    const int tid = threadIdx.x;
    const int lane = tid & 31;
    const int warp = tid >> 5;
    const int wm = warp & 3;
    const int wn = warp >> 2;
    const int qr = lane >> 2;
    const int qc = lane & 3;
    const int rowBase = blockIdx.x * 128;

    if (STATS && tid < 128) { sSum[tid] = 0.f; sSq[tid] = 0.f; }

    float acc[2][8][4];
#pragma unroll
    for (int m = 0; m < 2; m++)
#pragma unroll
        for (int n = 0; n < 8; n++)
#pragma unroll
            for (int j = 0; j < 4; j++) acc[m][n][j] = 0.f;

    for (int kk = 0; kk < K; kk += 16) {
#pragma unroll
        for (int it = 0; it < 2; it++) {
            int f = it * 256 + tid;
            int row = f >> 2;
            int c4 = (f & 3) << 2;
            int gr = rowBase + row;
            float4 v = make_float4(0.f, 0.f, 0.f, 0.f);
            if (gr < NN) v = *(const float4*)(A + (size_t)gr * K + kk + c4);
            float vals[4] = {v.x, v.y, v.z, v.w};
#pragma unroll
            for (int j = 0; j < 4; j++) {
                float val = vals[j];
                if (IN_BN) {
                    int kb = kk + c4 + j;
                    val = fmaxf(val * g_scale[kb] + g_shift[kb], 0.f);
                }
                __nv_bfloat16 h = __float2bfloat16(val);
                sAhi[row * 16 + c4 + j] = h;
                sAlo[row * 16 + c4 + j] = __float2bfloat16(val - __bfloat162float(h));
            }
        }
        {
            int n = tid >> 1, half = tid & 1;
            *(uint4*)(sBhi + n * 16 + half * 8) =
                *(const uint4*)(pWhi + (size_t)n * K + kk + half * 8);
            *(uint4*)(sBlo + n * 16 + half * 8) =
                *(const uint4*)(pWlo + (size_t)n * K + kk + half * 8);
        }
        __syncthreads();

        const uint32_t* a32h = (const uint32_t*)sAhi;
        const uint32_t* a32l = (const uint32_t*)sAlo;
        const uint32_t* b32h = (const uint32_t*)sBhi;
        const uint32_t* b32l = (const uint32_t*)sBlo;

        uint32_t bh[8][2], bl[8][2];
#pragma unroll
        for (int n = 0; n < 8; n++) {
            int nrow = wn * 64 + n * 8 + qr;
            bh[n][0] = b32h[nrow * 8 + qc];
            bh[n][1] = b32h[nrow * 8 + 4 + qc];
            bl[n][0] = b32l[nrow * 8 + qc];
            bl[n][1] = b32l[nrow * 8 + 4 + qc];
        }
#pragma unroll
        for (int m = 0; m < 2; m++) {
            int r = wm * 32 + m * 16 + qr;
            uint32_t ah[4], al[4];
            ah[0] = a32h[r * 8 + qc];
            ah[1] = a32h[(r + 8) * 8 + qc];
            ah[2] = a32h[r * 8 + 4 + qc];
            ah[3] = a32h[(r + 8) * 8 + 4 + qc];
            al[0] = a32l[r * 8 + qc];
            al[1] = a32l[(r + 8) * 8 + qc];
            al[2] = a32l[r * 8 + 4 + qc];
            al[3] = a32l[(r + 8) * 8 + 4 + qc];
#pragma unroll
            for (int n = 0; n < 8; n++) {
                mma_bf16(acc[m][n], ah, bh[n]);
                mma_bf16(acc[m][n], ah, bl[n]);
                mma_bf16(acc[m][n], al, bh[n]);
            }
        }
        __syncthreads();
    }

    float cS[16], cQ[16];
    if (STATS) {
#pragma unroll
        for (int j = 0; j < 16; j++) { cS[j] = 0.f; cQ[j] = 0.f; }
    }

#pragma unroll
    for (int m = 0; m < 2; m++) {
        int r = rowBase + wm * 32 + m * 16 + qr;
#pragma unroll
        for (int n = 0; n < 8; n++) {
            int c = wn * 64 + n * 8 + qc * 2;
            float b0 = bias[c], b1 = bias[c + 1];
            float v0 = acc[m][n][0] + b0, v1 = acc[m][n][1] + b1;
            float v2 = acc[m][n][2] + b0, v3 = acc[m][n][3] + b1;
            if (OUT_RELU) {
                v0 = fmaxf(v0, 0.f); v1 = fmaxf(v1, 0.f);
                v2 = fmaxf(v2, 0.f); v3 = fmaxf(v3, 0.f);
            }
            if (r < NN) {
                *(float2*)(out + (size_t)r * 128 + c) = make_float2(v0, v1);
                if (STATS) {
                    cS[n * 2] += v0; cS[n * 2 + 1] += v1;
                    cQ[n * 2] += v0 * v0; cQ[n * 2 + 1] += v1 * v1;
                }
            }
            if (r + 8 < NN) {
                *(float2*)(out + (size_t)(r + 8) * 128 + c) = make_float2(v2, v3);
                if (STATS) {
                    cS[n * 2] += v2; cS[n * 2 + 1] += v3;
                    cQ[n * 2] += v2 * v2; cQ[n * 2 + 1] += v3 * v3;
                }
            }
        }
    }

    if (STATS) {
#pragma unroll
        for (int n = 0; n < 8; n++) {
            int c = wn * 64 + n * 8 + qc * 2;
            atomicAdd(&sSum[c], cS[n * 2]);
            atomicAdd(&sSum[c + 1], cS[n * 2 + 1]);
            atomicAdd(&sSq[c], cQ[n * 2]);
            atomicAdd(&sSq[c + 1], cQ[n * 2 + 1]);
        }
        __syncthreads();
        if (tid < 128) {
            atomicAdd(&g_Ssum[tid], sSum[tid]);
            atomicAdd(&g_Ssq[tid], sSq[tid]);
        }
    }
}

// =====================================================================
// Fused head: relu(bufC @ W[slot6] + hba) @ hwb + hbb -> out
// =====================================================================
__global__ void __launch_bounds__(256)
k_headgemm(const float* __restrict__ hba, const float* __restrict__ hwb,
           const float* __restrict__ hbb, float* __restrict__ out) {
    const float* A = (const float*)g_bufC;
    const __nv_bfloat16* pWhi = (const __nv_bfloat16*)g_WtHi + (size_t)6 * 16384;
    const __nv_bfloat16* pWlo = (const __nv_bfloat16*)g_WtLo + (size_t)6 * 16384;
    constexpr int K = 128;

    __shared__ __align__(16) __nv_bfloat16 sAhi[128 * 16];
    __shared__ __align__(16) __nv_bfloat16 sAlo[128 * 16];
    __shared__ __align__(16) __nv_bfloat16 sBhi[128 * 16];
    __shared__ __align__(16) __nv_bfloat16 sBlo[128 * 16];
    __shared__ float sW2[256];
    __shared__ float sOut[256];

    const int tid = threadIdx.x;
    const int lane = tid & 31;
    const int warp = tid >> 5;
    const int wm = warp & 3;
    const int wn = warp >> 2;
    const int qr = lane >> 2;
    const int qc = lane & 3;
    const int rowBase = blockIdx.x * 128;

    sW2[tid] = hwb[tid];
    sOut[tid] = 0.f;

    float acc[2][8][4];
#pragma unroll
    for (int m = 0; m < 2; m++)
#pragma unroll
        for (int n = 0; n < 8; n++)
#pragma unroll
            for (int j = 0; j < 4; j++) acc[m][n][j] = 0.f;

    for (int kk = 0; kk < K; kk += 16) {
#pragma unroll
        for (int it = 0; it < 2; it++) {
            int f = it * 256 + tid;
            int row = f >> 2;
            int c4 = (f & 3) << 2;
            int gr = rowBase + row;
            float4 v = make_float4(0.f, 0.f, 0.f, 0.f);
            if (gr < NN) v = *(const float4*)(A + (size_t)gr * K + kk + c4);
            float vals[4] = {v.x, v.y, v.z, v.w};
#pragma unroll
            for (int j = 0; j < 4; j++) {
                __nv_bfloat16 h = __float2bfloat16(vals[j]);
                sAhi[row * 16 + c4 + j] = h;
                sAlo[row * 16 + c4 + j] = __float2bfloat16(vals[j] - __bfloat162float(h));
            }
        }
        {
            int n = tid >> 1, half = tid & 1;
            *(uint4*)(sBhi + n * 16 + half * 8) =
                *(const uint4*)(pWhi + (size_t)n * K + kk + half * 8);
            *(uint4*)(sBlo + n * 16 + half * 8) =
                *(const uint4*)(pWlo + (size_t)n * K + kk + half * 8);
        }
        __syncthreads();

        const uint32_t* a32h = (const uint32_t*)sAhi;
        const uint32_t* a32l = (const uint32_t*)sAlo;
        const uint32_t* b32h = (const uint32_t*)sBhi;
        const uint32_t* b32l = (const uint32_t*)sBlo;

        uint32_t bh[8][2], bl[8][2];
#pragma unroll
        for (int n = 0; n < 8; n++) {
            int nrow = wn * 64 + n * 8 + qr;
            bh[n][0] = b32h[nrow * 8 + qc];
            bh[n][1] = b32h[nrow * 8 + 4 + qc];
            bl[n][0] = b32l[nrow * 8 + qc];
            bl[n][1] = b32l[nrow * 8 + 4 + qc];
        }
#pragma unroll
        for (int m = 0; m < 2; m++) {
            int r = wm * 32 + m * 16 + qr;
            uint32_t ah[4], al[4];
            ah[0] = a32h[r * 8 + qc];
            ah[1] = a32h[(r + 8) * 8 + qc];
            ah[2] = a32h[r * 8 + 4 + qc];
            ah[3] = a32h[(r + 8) * 8 + 4 + qc];
            al[0] = a32l[r * 8 + qc];
            al[1] = a32l[(r + 8) * 8 + qc];
            al[2] = a32l[r * 8 + 4 + qc];
            al[3] = a32l[(r + 8) * 8 + 4 + qc];
#pragma unroll
            for (int n = 0; n < 8; n++) {
                mma_bf16(acc[m][n], ah, bh[n]);
                mma_bf16(acc[m][n], ah, bl[n]);
                mma_bf16(acc[m][n], al, bh[n]);
            }
        }
        __syncthreads();
    }

    // epilogue: bias + relu, project 128 -> 2 via smem accumulation
#pragma unroll
    for (int m = 0; m < 2; m++) {
        int rl = wm * 32 + m * 16 + qr;
#pragma unroll
        for (int n = 0; n < 8; n++) {
            int c = wn * 64 + n * 8 + qc * 2;
            float b0 = hba[c], b1 = hba[c + 1];
            float v0 = fmaxf(acc[m][n][0] + b0, 0.f), v1 = fmaxf(acc[m][n][1] + b1, 0.f);
            float v2 = fmaxf(acc[m][n][2] + b0, 0.f), v3 = fmaxf(acc[m][n][3] + b1, 0.f);
            float w00 = sW2[c * 2 + 0], w01 = sW2[c * 2 + 1];
            float w10 = sW2[(c + 1) * 2 + 0], w11 = sW2[(c + 1) * 2 + 1];
            if (rowBase + rl < NN) {
                atomicAdd(&sOut[rl * 2 + 0], v0 * w00 + v1 * w10);
                atomicAdd(&sOut[rl * 2 + 1], v0 * w01 + v1 * w11);
            }
            if (rowBase + rl + 8 < NN) {
                atomicAdd(&sOut[(rl + 8) * 2 + 0], v2 * w00 + v3 * w10);
                atomicAdd(&sOut[(rl + 8) * 2 + 1], v2 * w01 + v3 * w11);
            }
        }
    }
    __syncthreads();
    if (tid < 128) {
        int r = rowBase + tid;
        if (r < NN) {
            out[(size_t)r * 2 + 0] = sOut[tid * 2 + 0] + hbb[0];
            out[(size_t)r * 2 + 1] = sOut[tid * 2 + 1] + hbb[1];
        }
    }
}

// ---------------- launch ----------------
extern "C" void kernel_launch(void* const* d_in, const int* in_sizes, int n_in,
                              void* d_out, int out_size) {
    const float* x = (const float*)d_in[0];
    const int* ei = (const int*)d_in[1];

    const float* wa[3]; const float* ba[3]; const float* gm[3]; const float* be[3];
    const float* wb[3]; const float* bb[3]; const float* ep[3];
    for (int l = 0; l < 3; l++) {
        int b = 2 + 7 * l;
        wa[l] = (const float*)d_in[b + 0];
        ba[l] = (const float*)d_in[b + 1];
        gm[l] = (const float*)d_in[b + 2];
        be[l] = (const float*)d_in[b + 3];
        wb[l] = (const float*)d_in[b + 4];
        bb[l] = (const float*)d_in[b + 5];
        ep[l] = (const float*)d_in[b + 6];
    }
    const float* hwa = (const float*)d_in[23];
    const float* hba = (const float*)d_in[24];
    const float* hwb = (const float*)d_in[25];
    const float* hbb = (const float*)d_in[26];
    float* out = (float*)d_out;

    const int NB1 = (NN + 1023) / 1024;       // 98
    const int GB = (NN + 127) / 128;           // 782
    const int AGGB = (NN + 7) / 8;             // 12500

    // one-shot weight pre-split (slots: 0=wa0(K64),1=wb0,2=wa1,3=wb1,4=wa2,5=wb2,6=hwa)
    dim3 pg(64, 7);
    k_prepAll<<<pg, 256>>>(wa[0], wb[0], wa[1], wb[1], wa[2], wb[2], hwa);

    // edge dtype detection + CSR build
    k_detect<<<1, 256>>>(ei);
    k_zero_counts<<<(NN + 255) / 256, 256>>>();
    k_hist<<<(NE + 255) / 256, 256>>>(ei);
    k_scan1<<<NB1, 1024>>>();
    k_scan2<<<1, 128>>>(NB1);
    k_scan3<<<NB1, 1024>>>();
    k_scatter<<<(NE + 255) / 256, 256>>>(ei);
    k_zero_stats<<<1, 128>>>();

    // ---- layer 0 (din = 64): x -> bufA -> bufB -> bufC ----
    k_agg64<<<AGGB, 256>>>(x, ep[0]);
    k_gemm_mma<64, 0, 1, 0, false, false, true><<<GB, 256>>>(ba[0]);
    k_bn_finalize<<<1, 128>>>(gm[0], be[0]);
    k_gemm_mma<128, 1, 2, 1, true, true, false><<<GB, 256>>>(bb[0]);

    // ---- layer 1 ----
    k_agg128<<<AGGB, 256>>>(ep[1]);
    k_gemm_mma<128, 0, 1, 2, false, false, true><<<GB, 256>>>(ba[1]);
    k_bn_finalize<<<1, 128>>>(gm[1], be[1]);
    k_gemm_mma<128, 1, 2, 3, true, true, false><<<GB, 256>>>(bb[1]);

    // ---- layer 2 ----
    k_agg128<<<AGGB, 256>>>(ep[2]);
    k_gemm_mma<128, 0, 1, 4, false, false, true><<<GB, 256>>>(ba[2]);
    k_bn_finalize<<<1, 128>>>(gm[2], be[2]);
    k_gemm_mma<128, 1, 2, 5, true, true, false><<<GB, 256>>>(bb[2]);

    // ---- fused head: bufC -> out ----
    k_headgemm<<<GB, 256>>>(hba, hwb, hbb, out);
}